// round 5
// baseline (speedup 1.0000x reference)
#include <cuda_runtime.h>
#include <math.h>

#define NN 50000
#define NE 800000
#define HD 128
#define OD 64

typedef unsigned long long ull;

// Scratch (device globals: no allocation allowed in kernel_launch)
__device__ __align__(16) float g_bufA[NN * HD];
__device__ __align__(16) float g_bufB[NN * HD];
__device__ float g_dinv[NN];
__device__ int g_count[NN];
__device__ int g_rowstart[NN + 1];
__device__ int g_cursor[NN];
__device__ __align__(16) int2 g_cedge[NE];   // (src, bitcast norm)
__device__ int g_is64;

// Packed fp32x2 FMA (Blackwell FFMA2, PTX-only path)
__device__ __forceinline__ void ffma2(ull& d, ull a, ull b) {
    asm("fma.rn.f32x2 %0, %1, %2, %0;" : "+l"(d) : "l"(a), "l"(b));
}

// ---------------------------------------------------------------------------
// Preprocess 1: zero degree counts + detect edge dtype (int64 LE has zero odd
// 32-bit words since all values < 50000).
// ---------------------------------------------------------------------------
__global__ void pre_kernel(const unsigned* __restrict__ p) {
    int i = blockIdx.x * blockDim.x + threadIdx.x;
    if (i < NN) g_count[i] = 0;
    if (i == 0) {
        int is64 = 1;
        for (int w = 1; w < 128; w += 2)
            if (p[w] != 0u) { is64 = 0; break; }
        g_is64 = is64;
    }
}

// Preprocess 2: in-degree histogram (reads only the dst half of edge_index).
__global__ void count_kernel(const void* __restrict__ ei) {
    int e = blockIdx.x * blockDim.x + threadIdx.x;
    if (e >= NE) return;
    int d;
    if (g_is64) d = (int)((const long long*)ei)[NE + e];
    else        d = ((const int*)ei)[NE + e];
    atomicAdd(&g_count[d], 1);
}

// Preprocess 3: single-block exclusive scan of counts -> rowstart/cursor,
// plus dinv = rsqrt(deg + 1) (self-loop included).
__global__ void scan_kernel() {
    __shared__ int partial[1024];
    const int tid = threadIdx.x;
    const int CH = (NN + 1023) / 1024;  // 49
    const int i0 = tid * CH;
    const int i1 = min(i0 + CH, NN);

    int sum = 0;
    for (int i = i0; i < i1; i++) sum += g_count[i];
    partial[tid] = sum;
    __syncthreads();
    for (int off = 1; off < 1024; off <<= 1) {
        int v = (tid >= off) ? partial[tid - off] : 0;
        __syncthreads();
        partial[tid] += v;
        __syncthreads();
    }
    int run = (tid > 0) ? partial[tid - 1] : 0;
    for (int i = i0; i < i1; i++) {
        g_rowstart[i] = run;
        g_cursor[i] = run;
        int c = g_count[i];
        run += c;
        g_dinv[i] = rsqrtf((float)c + 1.f);
    }
    if (tid == 0) g_rowstart[NN] = NE;
}

// Preprocess 4: bucket-fill CSR with packed (src, norm) records, straight
// from the original edge tensor (no intermediate src/dst arrays).
__global__ void fill_kernel(const void* __restrict__ ei) {
    int e = blockIdx.x * blockDim.x + threadIdx.x;
    if (e >= NE) return;
    int s, d;
    if (g_is64) {
        const long long* p = (const long long*)ei;
        s = (int)p[e];
        d = (int)p[NE + e];
    } else {
        const int* p = (const int*)ei;
        s = p[e];
        d = p[NE + e];
    }
    int pos = atomicAdd(&g_cursor[d], 1);
    float nm = g_dinv[s] * g_dinv[d];
    g_cedge[pos] = make_int2(s, __float_as_int(nm));
}

// ---------------------------------------------------------------------------
// Conv GEMM: out = act(A) @ W, act = relu(.+inb) if inb.
// 512 threads, 128-row tile. k-pair packed FFMA2: W staged in smem as
// (W[2k][c], W[2k+1][c]) f32x2 pairs; A read as float2 over (2k, 2k+1).
// ---------------------------------------------------------------------------
__global__ void __launch_bounds__(512, 1)
conv_gemm_kernel(const float* __restrict__ A,
                 const float* __restrict__ inb,
                 const float* __restrict__ W,
                 float* __restrict__ out) {
    extern __shared__ float sm[];
    float* Wp  = sm;             // 64 kpairs * 128 cols * 2 = 16384 floats
    float* Ash = sm + 16384;     // 128 rows * 128 k
    const int tid = threadIdx.x;
    const int row0 = blockIdx.x * 128;

    // Stage W into pair layout: ull index kp*128 + c
    for (int i = tid; i < 4096; i += 512) {
        int k = i >> 5;           // source row
        int c4 = i & 31;          // float4 col group
        float4 v = ((const float4*)W)[i];
        float* base = Wp + (k >> 1) * 256 + c4 * 8 + (k & 1);
        base[0] = v.x; base[2] = v.y; base[4] = v.z; base[6] = v.w;
    }
    // Stage A tile (fused prev-layer bias+relu)
    for (int i = tid; i < 128 * 32; i += 512) {
        int r = i >> 5, q = i & 31;
        int grow = row0 + r;
        float4 v = make_float4(0.f, 0.f, 0.f, 0.f);
        if (grow < NN) {
            v = ((const float4*)A)[grow * 32 + q];
            if (inb) {
                const float4 b = ((const float4*)inb)[q];
                v.x = fmaxf(v.x + b.x, 0.f);
                v.y = fmaxf(v.y + b.y, 0.f);
                v.z = fmaxf(v.z + b.z, 0.f);
                v.w = fmaxf(v.w + b.w, 0.f);
            }
        }
        ((float4*)Ash)[i] = v;
    }
    __syncthreads();

    const ull* Wp2 = (const ull*)Wp;
    const int cx = tid & 15;
    const int ry = (tid >> 4) * 4;

    ull acc[4][8];
    #pragma unroll
    for (int r = 0; r < 4; r++)
        #pragma unroll
        for (int j = 0; j < 8; j++) acc[r][j] = 0ull;

    #pragma unroll 2
    for (int kp = 0; kp < 64; kp++) {
        ull w[8];
        #pragma unroll
        for (int j = 0; j < 8; j++) w[j] = Wp2[kp * 128 + cx + 16 * j];
        #pragma unroll
        for (int r = 0; r < 4; r++) {
            ull a2 = *(const ull*)(Ash + (ry + r) * 128 + kp * 2);
            #pragma unroll
            for (int j = 0; j < 8; j++) ffma2(acc[r][j], a2, w[j]);
        }
    }

    #pragma unroll
    for (int r = 0; r < 4; r++) {
        int grow = row0 + ry + r;
        if (grow >= NN) continue;
        #pragma unroll
        for (int j = 0; j < 8; j++) {
            float2 p = *(float2*)&acc[r][j];
            out[grow * HD + cx + 16 * j] = p.x + p.y;
        }
    }
}

// ---------------------------------------------------------------------------
// CSR gather aggregation: ONE WARP PER CTA, one destination node per CTA.
// No intra-block straggler coupling (degrees are Poisson; a wide block waits
// on its slowest warp). Unrolled x4 with independent row loads (MLP=4).
// Self-loop folded into the accumulator init.
// ---------------------------------------------------------------------------
__global__ void __launch_bounds__(32)
gather_kernel(const float* __restrict__ t, float* __restrict__ out) {
    const int d = blockIdx.x;
    const int lane = threadIdx.x;

    float dd = g_dinv[d];
    float4 acc = ((const float4*)(t + d * HD))[lane];
    float s2 = dd * dd;
    acc.x *= s2; acc.y *= s2; acc.z *= s2; acc.w *= s2;

    int j = g_rowstart[d];
    const int end = g_rowstart[d + 1];

    for (; j + 4 <= end; j += 4) {
        int2 e0 = g_cedge[j];
        int2 e1 = g_cedge[j + 1];
        int2 e2 = g_cedge[j + 2];
        int2 e3 = g_cedge[j + 3];
        float4 v0 = ((const float4*)(t + e0.x * HD))[lane];
        float4 v1 = ((const float4*)(t + e1.x * HD))[lane];
        float4 v2 = ((const float4*)(t + e2.x * HD))[lane];
        float4 v3 = ((const float4*)(t + e3.x * HD))[lane];
        float n0 = __int_as_float(e0.y);
        float n1 = __int_as_float(e1.y);
        float n2 = __int_as_float(e2.y);
        float n3 = __int_as_float(e3.y);
        acc.x = fmaf(v0.x, n0, acc.x);
        acc.y = fmaf(v0.y, n0, acc.y);
        acc.z = fmaf(v0.z, n0, acc.z);
        acc.w = fmaf(v0.w, n0, acc.w);
        acc.x = fmaf(v1.x, n1, acc.x);
        acc.y = fmaf(v1.y, n1, acc.y);
        acc.z = fmaf(v1.z, n1, acc.z);
        acc.w = fmaf(v1.w, n1, acc.w);
        acc.x = fmaf(v2.x, n2, acc.x);
        acc.y = fmaf(v2.y, n2, acc.y);
        acc.z = fmaf(v2.z, n2, acc.z);
        acc.w = fmaf(v2.w, n2, acc.w);
        acc.x = fmaf(v3.x, n3, acc.x);
        acc.y = fmaf(v3.y, n3, acc.y);
        acc.z = fmaf(v3.z, n3, acc.z);
        acc.w = fmaf(v3.w, n3, acc.w);
    }
    for (; j < end; j++) {
        int2 e0 = g_cedge[j];
        float n0 = __int_as_float(e0.y);
        float4 v0 = ((const float4*)(t + e0.x * HD))[lane];
        acc.x = fmaf(v0.x, n0, acc.x);
        acc.y = fmaf(v0.y, n0, acc.y);
        acc.z = fmaf(v0.z, n0, acc.z);
        acc.w = fmaf(v0.w, n0, acc.w);
    }
    ((float4*)(out + d * HD))[lane] = acc;
}

// ---------------------------------------------------------------------------
// Fused dense head: out = sigmoid( relu( relu(A+b3) @ Wd1 + bd1 ) @ Wd2 + bd2 )
// ---------------------------------------------------------------------------
__global__ void __launch_bounds__(512, 1)
dense_kernel(const float* __restrict__ A,
             const float* __restrict__ b3,
             const float* __restrict__ Wd1,
             const float* __restrict__ bd1,
             const float* __restrict__ Wd2,
             const float* __restrict__ bd2,
             float* __restrict__ out) {
    extern __shared__ float sm[];
    float* W1p = sm;             // 16384
    float* W2p = sm + 16384;     // 8192 (64 kpairs * 64 cols * 2)
    float* Ash = sm + 24576;     // 16384
    const int tid = threadIdx.x;
    const int row0 = blockIdx.x * 128;

    for (int i = tid; i < 4096; i += 512) {
        int k = i >> 5, c4 = i & 31;
        float4 v = ((const float4*)Wd1)[i];
        float* base = W1p + (k >> 1) * 256 + c4 * 8 + (k & 1);
        base[0] = v.x; base[2] = v.y; base[4] = v.z; base[6] = v.w;
    }
    for (int i = tid; i < 2048; i += 512) {
        int k = i >> 4, c4 = i & 15;
        float4 v = ((const float4*)Wd2)[i];
        float* base = W2p + (k >> 1) * 128 + c4 * 8 + (k & 1);
        base[0] = v.x; base[2] = v.y; base[4] = v.z; base[6] = v.w;
    }
    for (int i = tid; i < 128 * 32; i += 512) {
        int r = i >> 5, q = i & 31;
        int grow = row0 + r;
        float4 v = make_float4(0.f, 0.f, 0.f, 0.f);
        if (grow < NN) {
            v = ((const float4*)A)[grow * 32 + q];
            const float4 b = ((const float4*)b3)[q];
            v.x = fmaxf(v.x + b.x, 0.f);
            v.y = fmaxf(v.y + b.y, 0.f);
            v.z = fmaxf(v.z + b.z, 0.f);
            v.w = fmaxf(v.w + b.w, 0.f);
        }
        ((float4*)Ash)[i] = v;
    }
    __syncthreads();

    // ---- GEMM1: h1 = relu(A @ Wd1 + bd1) ----
    const ull* W1p2 = (const ull*)W1p;
    const int cx = tid & 15;
    const int ry = (tid >> 4) * 4;

    ull acc[4][8];
    #pragma unroll
    for (int r = 0; r < 4; r++)
        #pragma unroll
        for (int j = 0; j < 8; j++) acc[r][j] = 0ull;

    #pragma unroll 2
    for (int kp = 0; kp < 64; kp++) {
        ull w[8];
        #pragma unroll
        for (int j = 0; j < 8; j++) w[j] = W1p2[kp * 128 + cx + 16 * j];
        #pragma unroll
        for (int r = 0; r < 4; r++) {
            ull a2 = *(const ull*)(Ash + (ry + r) * 128 + kp * 2);
            #pragma unroll
            for (int j = 0; j < 8; j++) ffma2(acc[r][j], a2, w[j]);
        }
    }

    float h[4][8];
    #pragma unroll
    for (int r = 0; r < 4; r++)
        #pragma unroll
        for (int j = 0; j < 8; j++) {
            float2 p = *(float2*)&acc[r][j];
            h[r][j] = fmaxf(p.x + p.y + bd1[cx + 16 * j], 0.f);
        }

    __syncthreads();
    #pragma unroll
    for (int r = 0; r < 4; r++)
        #pragma unroll
        for (int j = 0; j < 8; j++)
            Ash[(ry + r) * 128 + cx + 16 * j] = h[r][j];
    __syncthreads();

    // ---- GEMM2: out = sigmoid(h1 @ Wd2 + bd2) ----
    const ull* W2p2 = (const ull*)W2p;
    const int cx2 = tid & 7;            // cols = cx2 + 8j
    const int ry2 = (tid >> 3) * 2;     // 2 rows per thread

    ull acc2[2][8];
    #pragma unroll
    for (int r = 0; r < 2; r++)
        #pragma unroll
        for (int j = 0; j < 8; j++) acc2[r][j] = 0ull;

    #pragma unroll 2
    for (int kp = 0; kp < 64; kp++) {
        ull w[8];
        #pragma unroll
        for (int j = 0; j < 8; j++) w[j] = W2p2[kp * 64 + cx2 + 8 * j];
        #pragma unroll
        for (int r = 0; r < 2; r++) {
            ull a2 = *(const ull*)(Ash + (ry2 + r) * 128 + kp * 2);
            #pragma unroll
            for (int j = 0; j < 8; j++) ffma2(acc2[r][j], a2, w[j]);
        }
    }

    #pragma unroll
    for (int r = 0; r < 2; r++) {
        int grow = row0 + ry2 + r;
        if (grow >= NN) continue;
        #pragma unroll
        for (int j = 0; j < 8; j++) {
            float2 p = *(float2*)&acc2[r][j];
            float v = p.x + p.y + bd2[cx2 + 8 * j];
            out[grow * OD + cx2 + 8 * j] = 1.f / (1.f + __expf(-v));
        }
    }
}

// ---------------------------------------------------------------------------
extern "C" void kernel_launch(void* const* d_in, const int* in_sizes, int n_in,
                              void* d_out, int out_size) {
    const float* x   = (const float*)d_in[0];
    const void*  ei  = d_in[1];
    const float* W1  = (const float*)d_in[2];
    const float* b1  = (const float*)d_in[3];
    const float* W2  = (const float*)d_in[4];
    const float* b2  = (const float*)d_in[5];
    const float* W3  = (const float*)d_in[6];
    const float* b3  = (const float*)d_in[7];
    const float* Wd1 = (const float*)d_in[8];
    const float* bd1 = (const float*)d_in[9];
    const float* Wd2 = (const float*)d_in[10];
    const float* bd2 = (const float*)d_in[11];
    float* out = (float*)d_out;

    float *bufA, *bufB;
    cudaGetSymbolAddress((void**)&bufA, g_bufA);
    cudaGetSymbolAddress((void**)&bufB, g_bufB);

    const int smem_conv  = (16384 + 16384) * (int)sizeof(float);          // 128 KB
    const int smem_dense = (16384 + 8192 + 16384) * (int)sizeof(float);   // 160 KB
    cudaFuncSetAttribute((const void*)conv_gemm_kernel,
                         cudaFuncAttributeMaxDynamicSharedMemorySize, smem_conv);
    cudaFuncSetAttribute((const void*)dense_kernel,
                         cudaFuncAttributeMaxDynamicSharedMemorySize, smem_dense);

    const int gblocks = (NN + 127) / 128;      // 391
    const int eblocks = (NE + 255) / 256;      // 3125
    const int nblocks = (NN + 255) / 256;      // 196

    // Preprocess: degrees, dinv, CSR with fused per-edge norms
    pre_kernel<<<nblocks, 256>>>((const unsigned*)ei);
    count_kernel<<<eblocks, 256>>>(ei);
    scan_kernel<<<1, 1024>>>();
    fill_kernel<<<eblocks, 256>>>(ei);

    // Conv layer 1
    conv_gemm_kernel<<<gblocks, 512, smem_conv>>>(x, nullptr, W1, bufA);
    gather_kernel<<<NN, 32>>>(bufA, bufB);

    // Conv layer 2 (bias+relu of layer 1 fused into A-load)
    conv_gemm_kernel<<<gblocks, 512, smem_conv>>>(bufB, b1, W2, bufA);
    gather_kernel<<<NN, 32>>>(bufA, bufB);

    // Conv layer 3
    conv_gemm_kernel<<<gblocks, 512, smem_conv>>>(bufB, b2, W3, bufA);
    gather_kernel<<<NN, 32>>>(bufA, bufB);

    // Fused dense head
    dense_kernel<<<gblocks, 512, smem_dense>>>(bufB, b3, Wd1, bd1, Wd2, bd2, out);
}

// round 6
// speedup vs baseline: 1.0706x; 1.0706x over previous
#include <cuda_runtime.h>
#include <cuda_fp16.h>
#include <math.h>

#define NN 50000
#define NE 800000
#define HD 128
#define OD 64

typedef unsigned long long ull;

// Scratch (device globals: no allocation allowed in kernel_launch)
__device__ __align__(16) __half g_bufH[NN * HD];   // fp16 transformed features
__device__ __align__(16) float g_bufB[NN * HD];    // fp32 aggregated features
__device__ float g_dinv[NN];
__device__ int g_count[NN];
__device__ int g_rowstart[NN + 1];
__device__ int g_cursor[NN];
__device__ __align__(16) int2 g_cedge[NE];   // (src, bitcast norm)
__device__ int g_is64;

// Packed fp32x2 FMA (Blackwell FFMA2, PTX-only path)
__device__ __forceinline__ void ffma2(ull& d, ull a, ull b) {
    asm("fma.rn.f32x2 %0, %1, %2, %0;" : "+l"(d) : "l"(a), "l"(b));
}

// ---------------------------------------------------------------------------
// Preprocess 1: zero degree counts + detect edge dtype (int64 LE has zero odd
// 32-bit words since all values < 50000).
// ---------------------------------------------------------------------------
__global__ void pre_kernel(const unsigned* __restrict__ p) {
    int i = blockIdx.x * blockDim.x + threadIdx.x;
    if (i < NN) g_count[i] = 0;
    if (i == 0) {
        int is64 = 1;
        for (int w = 1; w < 128; w += 2)
            if (p[w] != 0u) { is64 = 0; break; }
        g_is64 = is64;
    }
}

// Preprocess 2: in-degree histogram (reads only the dst half of edge_index).
__global__ void count_kernel(const void* __restrict__ ei) {
    int e = blockIdx.x * blockDim.x + threadIdx.x;
    if (e >= NE) return;
    int d;
    if (g_is64) d = (int)((const long long*)ei)[NE + e];
    else        d = ((const int*)ei)[NE + e];
    atomicAdd(&g_count[d], 1);
}

// Preprocess 3: single-block exclusive scan of counts -> rowstart/cursor,
// plus dinv = rsqrt(deg + 1) (self-loop included).
__global__ void scan_kernel() {
    __shared__ int partial[1024];
    const int tid = threadIdx.x;
    const int CH = (NN + 1023) / 1024;  // 49
    const int i0 = tid * CH;
    const int i1 = min(i0 + CH, NN);

    int sum = 0;
    for (int i = i0; i < i1; i++) sum += g_count[i];
    partial[tid] = sum;
    __syncthreads();
    for (int off = 1; off < 1024; off <<= 1) {
        int v = (tid >= off) ? partial[tid - off] : 0;
        __syncthreads();
        partial[tid] += v;
        __syncthreads();
    }
    int run = (tid > 0) ? partial[tid - 1] : 0;
    for (int i = i0; i < i1; i++) {
        g_rowstart[i] = run;
        g_cursor[i] = run;
        int c = g_count[i];
        run += c;
        g_dinv[i] = rsqrtf((float)c + 1.f);
    }
    if (tid == 0) g_rowstart[NN] = NE;
}

// Preprocess 4: bucket-fill CSR with packed (src, norm) records, straight
// from the original edge tensor.
__global__ void fill_kernel(const void* __restrict__ ei) {
    int e = blockIdx.x * blockDim.x + threadIdx.x;
    if (e >= NE) return;
    int s, d;
    if (g_is64) {
        const long long* p = (const long long*)ei;
        s = (int)p[e];
        d = (int)p[NE + e];
    } else {
        const int* p = (const int*)ei;
        s = p[e];
        d = p[NE + e];
    }
    int pos = atomicAdd(&g_cursor[d], 1);
    float nm = g_dinv[s] * g_dinv[d];
    g_cedge[pos] = make_int2(s, __float_as_int(nm));
}

// ---------------------------------------------------------------------------
// Conv GEMM: t = act(A) @ W (fp32 accum), written as fp16.
// 512 threads, 128-row tile. k-pair packed FFMA2 mainloop.
// ---------------------------------------------------------------------------
__global__ void __launch_bounds__(512, 1)
conv_gemm_kernel(const float* __restrict__ A,
                 const float* __restrict__ inb,
                 const float* __restrict__ W,
                 __half* __restrict__ out) {
    extern __shared__ float sm[];
    float* Wp  = sm;             // 64 kpairs * 128 cols * 2 = 16384 floats
    float* Ash = sm + 16384;     // 128 rows * 128 k
    const int tid = threadIdx.x;
    const int row0 = blockIdx.x * 128;

    // Stage W into pair layout: ull index kp*128 + c
    for (int i = tid; i < 4096; i += 512) {
        int k = i >> 5;           // source row
        int c4 = i & 31;          // float4 col group
        float4 v = ((const float4*)W)[i];
        float* base = Wp + (k >> 1) * 256 + c4 * 8 + (k & 1);
        base[0] = v.x; base[2] = v.y; base[4] = v.z; base[6] = v.w;
    }
    // Stage A tile (fused prev-layer bias+relu)
    for (int i = tid; i < 128 * 32; i += 512) {
        int r = i >> 5, q = i & 31;
        int grow = row0 + r;
        float4 v = make_float4(0.f, 0.f, 0.f, 0.f);
        if (grow < NN) {
            v = ((const float4*)A)[grow * 32 + q];
            if (inb) {
                const float4 b = ((const float4*)inb)[q];
                v.x = fmaxf(v.x + b.x, 0.f);
                v.y = fmaxf(v.y + b.y, 0.f);
                v.z = fmaxf(v.z + b.z, 0.f);
                v.w = fmaxf(v.w + b.w, 0.f);
            }
        }
        ((float4*)Ash)[i] = v;
    }
    __syncthreads();

    const ull* Wp2 = (const ull*)Wp;
    const int cx = tid & 15;
    const int ry = (tid >> 4) * 4;

    ull acc[4][8];
    #pragma unroll
    for (int r = 0; r < 4; r++)
        #pragma unroll
        for (int j = 0; j < 8; j++) acc[r][j] = 0ull;

    #pragma unroll 2
    for (int kp = 0; kp < 64; kp++) {
        ull w[8];
        #pragma unroll
        for (int j = 0; j < 8; j++) w[j] = Wp2[kp * 128 + cx + 16 * j];
        #pragma unroll
        for (int r = 0; r < 4; r++) {
            ull a2 = *(const ull*)(Ash + (ry + r) * 128 + kp * 2);
            #pragma unroll
            for (int j = 0; j < 8; j++) ffma2(acc[r][j], a2, w[j]);
        }
    }

    #pragma unroll
    for (int r = 0; r < 4; r++) {
        int grow = row0 + ry + r;
        if (grow >= NN) continue;
        #pragma unroll
        for (int j = 0; j < 8; j++) {
            float2 p = *(float2*)&acc[r][j];
            out[grow * HD + cx + 16 * j] = __float2half_rn(p.x + p.y);
        }
    }
}

// ---------------------------------------------------------------------------
// CSR gather aggregation: one warp per destination node, fp16 source rows
// (256 B/row), fp32 accumulation, fp32 output. Unrolled x4 (MLP=4).
// Self-loop folded into the accumulator init.
// ---------------------------------------------------------------------------
__device__ __forceinline__ void acc_row(float4& acc, uint2 u, float nm) {
    float2 a = __half22float2(*(const __half2*)&u.x);
    float2 b = __half22float2(*(const __half2*)&u.y);
    acc.x = fmaf(a.x, nm, acc.x);
    acc.y = fmaf(a.y, nm, acc.y);
    acc.z = fmaf(b.x, nm, acc.z);
    acc.w = fmaf(b.y, nm, acc.w);
}

__global__ void gather_kernel(const __half* __restrict__ t,
                              float* __restrict__ out) {
    int gid = blockIdx.x * blockDim.x + threadIdx.x;
    int d = gid >> 5;
    int lane = gid & 31;
    if (d >= NN) return;

    float dd = g_dinv[d];
    float4 acc = make_float4(0.f, 0.f, 0.f, 0.f);
    acc_row(acc, ((const uint2*)(t + d * HD))[lane], dd * dd);

    int j = g_rowstart[d];
    const int end = g_rowstart[d + 1];

    for (; j + 4 <= end; j += 4) {
        int2 e0 = g_cedge[j];
        int2 e1 = g_cedge[j + 1];
        int2 e2 = g_cedge[j + 2];
        int2 e3 = g_cedge[j + 3];
        uint2 u0 = ((const uint2*)(t + e0.x * HD))[lane];
        uint2 u1 = ((const uint2*)(t + e1.x * HD))[lane];
        uint2 u2 = ((const uint2*)(t + e2.x * HD))[lane];
        uint2 u3 = ((const uint2*)(t + e3.x * HD))[lane];
        acc_row(acc, u0, __int_as_float(e0.y));
        acc_row(acc, u1, __int_as_float(e1.y));
        acc_row(acc, u2, __int_as_float(e2.y));
        acc_row(acc, u3, __int_as_float(e3.y));
    }
    for (; j < end; j++) {
        int2 e0 = g_cedge[j];
        uint2 u0 = ((const uint2*)(t + e0.x * HD))[lane];
        acc_row(acc, u0, __int_as_float(e0.y));
    }
    ((float4*)(out + d * HD))[lane] = acc;
}

// ---------------------------------------------------------------------------
// Fused dense head: out = sigmoid( relu( relu(A+b3) @ Wd1 + bd1 ) @ Wd2 + bd2 )
// ---------------------------------------------------------------------------
__global__ void __launch_bounds__(512, 1)
dense_kernel(const float* __restrict__ A,
             const float* __restrict__ b3,
             const float* __restrict__ Wd1,
             const float* __restrict__ bd1,
             const float* __restrict__ Wd2,
             const float* __restrict__ bd2,
             float* __restrict__ out) {
    extern __shared__ float sm[];
    float* W1p = sm;             // 16384
    float* W2p = sm + 16384;     // 8192 (64 kpairs * 64 cols * 2)
    float* Ash = sm + 24576;     // 16384
    const int tid = threadIdx.x;
    const int row0 = blockIdx.x * 128;

    for (int i = tid; i < 4096; i += 512) {
        int k = i >> 5, c4 = i & 31;
        float4 v = ((const float4*)Wd1)[i];
        float* base = W1p + (k >> 1) * 256 + c4 * 8 + (k & 1);
        base[0] = v.x; base[2] = v.y; base[4] = v.z; base[6] = v.w;
    }
    for (int i = tid; i < 2048; i += 512) {
        int k = i >> 4, c4 = i & 15;
        float4 v = ((const float4*)Wd2)[i];
        float* base = W2p + (k >> 1) * 128 + c4 * 8 + (k & 1);
        base[0] = v.x; base[2] = v.y; base[4] = v.z; base[6] = v.w;
    }
    for (int i = tid; i < 128 * 32; i += 512) {
        int r = i >> 5, q = i & 31;
        int grow = row0 + r;
        float4 v = make_float4(0.f, 0.f, 0.f, 0.f);
        if (grow < NN) {
            v = ((const float4*)A)[grow * 32 + q];
            const float4 b = ((const float4*)b3)[q];
            v.x = fmaxf(v.x + b.x, 0.f);
            v.y = fmaxf(v.y + b.y, 0.f);
            v.z = fmaxf(v.z + b.z, 0.f);
            v.w = fmaxf(v.w + b.w, 0.f);
        }
        ((float4*)Ash)[i] = v;
    }
    __syncthreads();

    // ---- GEMM1: h1 = relu(A @ Wd1 + bd1) ----
    const ull* W1p2 = (const ull*)W1p;
    const int cx = tid & 15;
    const int ry = (tid >> 4) * 4;

    ull acc[4][8];
    #pragma unroll
    for (int r = 0; r < 4; r++)
        #pragma unroll
        for (int j = 0; j < 8; j++) acc[r][j] = 0ull;

    #pragma unroll 2
    for (int kp = 0; kp < 64; kp++) {
        ull w[8];
        #pragma unroll
        for (int j = 0; j < 8; j++) w[j] = W1p2[kp * 128 + cx + 16 * j];
        #pragma unroll
        for (int r = 0; r < 4; r++) {
            ull a2 = *(const ull*)(Ash + (ry + r) * 128 + kp * 2);
            #pragma unroll
            for (int j = 0; j < 8; j++) ffma2(acc[r][j], a2, w[j]);
        }
    }

    float h[4][8];
    #pragma unroll
    for (int r = 0; r < 4; r++)
        #pragma unroll
        for (int j = 0; j < 8; j++) {
            float2 p = *(float2*)&acc[r][j];
            h[r][j] = fmaxf(p.x + p.y + bd1[cx + 16 * j], 0.f);
        }

    __syncthreads();
    #pragma unroll
    for (int r = 0; r < 4; r++)
        #pragma unroll
        for (int j = 0; j < 8; j++)
            Ash[(ry + r) * 128 + cx + 16 * j] = h[r][j];
    __syncthreads();

    // ---- GEMM2: out = sigmoid(h1 @ Wd2 + bd2) ----
    const ull* W2p2 = (const ull*)W2p;
    const int cx2 = tid & 7;            // cols = cx2 + 8j
    const int ry2 = (tid >> 3) * 2;     // 2 rows per thread

    ull acc2[2][8];
    #pragma unroll
    for (int r = 0; r < 2; r++)
        #pragma unroll
        for (int j = 0; j < 8; j++) acc2[r][j] = 0ull;

    #pragma unroll 2
    for (int kp = 0; kp < 64; kp++) {
        ull w[8];
        #pragma unroll
        for (int j = 0; j < 8; j++) w[j] = W2p2[kp * 64 + cx2 + 8 * j];
        #pragma unroll
        for (int r = 0; r < 2; r++) {
            ull a2 = *(const ull*)(Ash + (ry2 + r) * 128 + kp * 2);
            #pragma unroll
            for (int j = 0; j < 8; j++) ffma2(acc2[r][j], a2, w[j]);
        }
    }

    #pragma unroll
    for (int r = 0; r < 2; r++) {
        int grow = row0 + ry2 + r;
        if (grow >= NN) continue;
        #pragma unroll
        for (int j = 0; j < 8; j++) {
            float2 p = *(float2*)&acc2[r][j];
            float v = p.x + p.y + bd2[cx2 + 8 * j];
            out[grow * OD + cx2 + 8 * j] = 1.f / (1.f + __expf(-v));
        }
    }
}

// ---------------------------------------------------------------------------
extern "C" void kernel_launch(void* const* d_in, const int* in_sizes, int n_in,
                              void* d_out, int out_size) {
    const float* x   = (const float*)d_in[0];
    const void*  ei  = d_in[1];
    const float* W1  = (const float*)d_in[2];
    const float* b1  = (const float*)d_in[3];
    const float* W2  = (const float*)d_in[4];
    const float* b2  = (const float*)d_in[5];
    const float* W3  = (const float*)d_in[6];
    const float* b3  = (const float*)d_in[7];
    const float* Wd1 = (const float*)d_in[8];
    const float* bd1 = (const float*)d_in[9];
    const float* Wd2 = (const float*)d_in[10];
    const float* bd2 = (const float*)d_in[11];
    float* out = (float*)d_out;

    __half* bufH;
    float* bufB;
    cudaGetSymbolAddress((void**)&bufH, g_bufH);
    cudaGetSymbolAddress((void**)&bufB, g_bufB);

    const int smem_conv  = (16384 + 16384) * (int)sizeof(float);          // 128 KB
    const int smem_dense = (16384 + 8192 + 16384) * (int)sizeof(float);   // 160 KB
    cudaFuncSetAttribute((const void*)conv_gemm_kernel,
                         cudaFuncAttributeMaxDynamicSharedMemorySize, smem_conv);
    cudaFuncSetAttribute((const void*)dense_kernel,
                         cudaFuncAttributeMaxDynamicSharedMemorySize, smem_dense);

    const int gblocks = (NN + 127) / 128;      // 391
    const int eblocks = (NE + 255) / 256;      // 3125
    const int nblocks = (NN + 255) / 256;      // 196
    const int wblocks = (NN * 32 + 255) / 256; // 6250

    // Preprocess: degrees, dinv, CSR with fused per-edge norms
    pre_kernel<<<nblocks, 256>>>((const unsigned*)ei);
    count_kernel<<<eblocks, 256>>>(ei);
    scan_kernel<<<1, 1024>>>();
    fill_kernel<<<eblocks, 256>>>(ei);

    // Conv layer 1
    conv_gemm_kernel<<<gblocks, 512, smem_conv>>>(x, nullptr, W1, bufH);
    gather_kernel<<<wblocks, 256>>>(bufH, bufB);

    // Conv layer 2 (bias+relu of layer 1 fused into A-load)
    conv_gemm_kernel<<<gblocks, 512, smem_conv>>>(bufB, b1, W2, bufH);
    gather_kernel<<<wblocks, 256>>>(bufH, bufB);

    // Conv layer 3
    conv_gemm_kernel<<<gblocks, 512, smem_conv>>>(bufB, b2, W3, bufH);
    gather_kernel<<<wblocks, 256>>>(bufH, bufB);

    // Fused dense head
    dense_kernel<<<gblocks, 512, smem_dense>>>(bufB, b3, Wd1, bd1, Wd2, bd2, out);
}